// round 5
// baseline (speedup 1.0000x reference)
#include <cuda_runtime.h>
#include <math.h>

#define NB 16
#define NC 64
#define NH 128
#define NW 128
#define NK 512
#define ND 64
#define NHW (NH*NW)            // 16384
#define NTOK (NB*NHW)          // 262144
#define QELEMS (NB*NC*NHW)     // 1048576
#define OFF_LOSS 0
#define OFF_Q 1
#define OFF_PERP (1 + QELEMS)  // 1048577
#define OFF_ENC (2 + QELEMS)   // 1048578
#define ENC_F ((long long)NTOK * NK)        // 134217728
#define ENC_V4 ((ENC_F - 4) / 4)            // 33554431 aligned float4 slots

__device__ int           g_idx[NTOK];
__device__ unsigned int  g_cnt[NK];
__device__ double        g_sum;
__device__ float         g_e2[NK];

__device__ __forceinline__ void fma2(unsigned long long& acc,
                                     unsigned long long a,
                                     unsigned long long b) {
    asm("fma.rn.f32x2 %0, %1, %2, %0;" : "+l"(acc) : "l"(a), "l"(b));
}
__device__ __forceinline__ float f2_lo(unsigned long long v) {
    return __uint_as_float((unsigned int)v);
}
__device__ __forceinline__ float f2_hi(unsigned long long v) {
    return __uint_as_float((unsigned int)(v >> 32));
}

// ---------------------------------------------------------------------------
// Kernel 0: zero counters, compute ||e_k||^2 with reference rounding
// ---------------------------------------------------------------------------
__global__ void k_init(const float* __restrict__ emb) {
    int k = threadIdx.x;
    if (k == 0) g_sum = 0.0;
    g_cnt[k] = 0u;
    const float* e = emb + k * ND;
    float s = 0.f;
    for (int d = 0; d < ND; d++) s = __fadd_rn(s, __fmul_rn(e[d], e[d]));
    g_e2[k] = s;
}

// ---------------------------------------------------------------------------
// Kernel 1: per-token argmin, register-tiled.
// CTA = 256 threads, 128 tokens. Thread = 4 tokens x 2 codes per 16-code chunk.
// Per d: 2x LDS.128 + 4 FFMA2 -> fma-pipe bound.
// Dot accumulates sequentially over d in one fp32 lane (bitwise == reference-
// matching round-1 order). Argmin tie-break: smallest code index (jnp.argmin
// first-occurrence semantics) — strict '<' within a thread (codes ascend),
// explicit index tie-break in the cross-group merge (groups interleave codes).
// ---------------------------------------------------------------------------
__global__ __launch_bounds__(256) void k_argmin(const float* __restrict__ x_in,
                                                const float* __restrict__ emb) {
    __shared__ float  sxt[64 * 128];     // [d][w]  32 KB
    __shared__ float2 se2x[64 * 18];     // [d][k] duplicated, row pad->18
    __shared__ float  se2s[16];

    const int tid = threadIdx.x;
    const int tg  = tid & 31;            // token group: tokens 4*tg..4*tg+3
    const int kg  = tid >> 5;            // code group: codes kg*2, kg*2+1 per chunk
    const int blk = blockIdx.x;
    const int b   = blk >> 7;
    const int hw0 = (blk & 127) << 7;

    // stage x tile (coalesced 128-float rows)
    const float* xb = x_in + (size_t)b * (NC * NHW) + hw0;
    for (int i = tid; i < 64 * 128; i += 256) {
        int d = i >> 7, w = i & 127;
        sxt[i] = xb[(size_t)d * NHW + w];
    }
    __syncthreads();

    // per-thread ||x||^2 for its 4 tokens (sequential d, separately rounded squares)
    float sx0 = 0.f, sx1 = 0.f, sx2 = 0.f, sx3 = 0.f;
    for (int d = 0; d < 64; d++) {
        float4 xv = *(const float4*)&sxt[d * 128 + 4 * tg];
        sx0 = __fadd_rn(sx0, __fmul_rn(xv.x, xv.x));
        sx1 = __fadd_rn(sx1, __fmul_rn(xv.y, xv.y));
        sx2 = __fadd_rn(sx2, __fmul_rn(xv.z, xv.z));
        sx3 = __fadd_rn(sx3, __fmul_rn(xv.w, xv.w));
    }

    float bestd0 = 3.4e38f, bestd1 = 3.4e38f, bestd2 = 3.4e38f, bestd3 = 3.4e38f;
    int   bk0 = 0, bk1 = 0, bk2 = 0, bk3 = 0;

#pragma unroll 1
    for (int kc = 0; kc < NK; kc += 16) {
        __syncthreads();
        {   // stage 16-code chunk, duplicated lanes
            const float* eb = emb + (size_t)kc * ND;
#pragma unroll
            for (int p = 0; p < 4; p++) {
                int i = p * 256 + tid;
                int k = i >> 6, d = i & 63;
                float v = eb[k * 64 + d];
                se2x[d * 18 + k] = make_float2(v, v);
            }
            if (tid < 16) se2s[tid] = g_e2[kc + tid];
        }
        __syncthreads();

        unsigned long long a00 = 0ull, a01 = 0ull, a10 = 0ull, a11 = 0ull;
#pragma unroll 4
        for (int d = 0; d < 64; d++) {
            ulonglong2 xp = *(const ulonglong2*)&sxt[d * 128 + 4 * tg];
            ulonglong2 ep = *(const ulonglong2*)&se2x[d * 18 + kg * 2];
            fma2(a00, xp.x, ep.x);
            fma2(a01, xp.x, ep.y);
            fma2(a10, xp.y, ep.x);
            fma2(a11, xp.y, ep.y);
        }

        const float e20 = se2s[kg * 2 + 0];
        const float e21 = se2s[kg * 2 + 1];
        const int c0 = kc + kg * 2, c1 = c0 + 1;

        float d00 = __fsub_rn(__fadd_rn(sx0, e20), 2.0f * f2_lo(a00));
        float d01 = __fsub_rn(__fadd_rn(sx0, e21), 2.0f * f2_lo(a01));
        float d10 = __fsub_rn(__fadd_rn(sx1, e20), 2.0f * f2_hi(a00));
        float d11 = __fsub_rn(__fadd_rn(sx1, e21), 2.0f * f2_hi(a01));
        float d20 = __fsub_rn(__fadd_rn(sx2, e20), 2.0f * f2_lo(a10));
        float d21 = __fsub_rn(__fadd_rn(sx2, e21), 2.0f * f2_lo(a11));
        float d30 = __fsub_rn(__fadd_rn(sx3, e20), 2.0f * f2_hi(a10));
        float d31 = __fsub_rn(__fadd_rn(sx3, e21), 2.0f * f2_hi(a11));

        if (d00 < bestd0) { bestd0 = d00; bk0 = c0; }
        if (d01 < bestd0) { bestd0 = d01; bk0 = c1; }
        if (d10 < bestd1) { bestd1 = d10; bk1 = c0; }
        if (d11 < bestd1) { bestd1 = d11; bk1 = c1; }
        if (d20 < bestd2) { bestd2 = d20; bk2 = c0; }
        if (d21 < bestd2) { bestd2 = d21; bk2 = c1; }
        if (d30 < bestd3) { bestd3 = d30; bk3 = c0; }
        if (d31 < bestd3) { bestd3 = d31; bk3 = c1; }
    }

    // cross-kgroup reduction (overlay scratch on sxt — all compute done)
    __syncthreads();
    float*    rb   = sxt;                         // [128][8]
    int*      rk   = (int*)(sxt + 1024);          // [128][8]
    unsigned* scnt = (unsigned*)(sxt + 2048);     // [512]

    rb[(4 * tg + 0) * 8 + kg] = bestd0;  rk[(4 * tg + 0) * 8 + kg] = bk0;
    rb[(4 * tg + 1) * 8 + kg] = bestd1;  rk[(4 * tg + 1) * 8 + kg] = bk1;
    rb[(4 * tg + 2) * 8 + kg] = bestd2;  rk[(4 * tg + 2) * 8 + kg] = bk2;
    rb[(4 * tg + 3) * 8 + kg] = bestd3;  rk[(4 * tg + 3) * 8 + kg] = bk3;
    for (int i = tid; i < NK; i += 256) scnt[i] = 0u;
    __syncthreads();

    if (tid < 128) {
        float bd = rb[tid * 8];
        int   bk = rk[tid * 8];
#pragma unroll
        for (int g = 1; g < 8; g++) {
            float dd = rb[tid * 8 + g];
            int   kk = rk[tid * 8 + g];
            // groups interleave codes: on equal distance pick SMALLER index
            // (jnp.argmin first-occurrence semantics)
            if (dd < bd || (dd == bd && kk < bk)) { bd = dd; bk = kk; }
        }
        g_idx[blk * 128 + tid] = bk;
        atomicAdd(&scnt[bk], 1u);
    }
    __syncthreads();
    for (int i = tid; i < NK; i += 256)
        if (scnt[i]) atomicAdd(&g_cnt[i], scnt[i]);
}

// ---------------------------------------------------------------------------
// Kernel 2: gather quantized rows, transpose to NCHW, accumulate loss sum.
// ---------------------------------------------------------------------------
__global__ __launch_bounds__(256) void k_quant(const float* __restrict__ x_in,
                                               const float* __restrict__ emb,
                                               float* __restrict__ out) {
    __shared__ float sq[128 * 65];
    __shared__ int   sidx[128];
    __shared__ float spart[8];

    const int tid = threadIdx.x;
    const int bh  = blockIdx.x;
    const int b   = bh >> 7;
    const int h   = bh & 127;

    if (tid < 128) sidx[tid] = g_idx[b * NHW + h * NW + tid];
    __syncthreads();

    for (int i = tid; i < 128 * ND; i += 256) {
        int w = i >> 6;
        int d = i & 63;
        sq[w * 65 + d] = emb[(size_t)sidx[w] * ND + d];
    }
    __syncthreads();

    const float* xb = x_in + (size_t)b * NC * NHW + h * NW;
    float*       qb = out + OFF_Q + (size_t)b * NC * NHW + h * NW;

    float ls = 0.f;
    for (int i = tid; i < NC * NW; i += 256) {
        int c = i >> 7;
        int w = i & 127;
        float q  = sq[w * 65 + c];
        float xv = xb[(size_t)c * NHW + w];
        float dd = q - xv;
        ls += dd * dd;
        qb[(size_t)c * NHW + w] = q;
    }

    for (int o = 16; o; o >>= 1) ls += __shfl_xor_sync(0xffffffffu, ls, o);
    if ((tid & 31) == 0) spart[tid >> 5] = ls;
    __syncthreads();
    if (tid == 0) {
        float s = 0.f;
        for (int i = 0; i < 8; i++) s += spart[i];
        atomicAdd(&g_sum, (double)s);
    }
}

// ---------------------------------------------------------------------------
// Kernel 3a: zero-fill encodings — pure aligned float4 stores, no loads.
// ---------------------------------------------------------------------------
__global__ __launch_bounds__(256) void k_enc_zero(float* __restrict__ out) {
    const long long gid = (long long)blockIdx.x * 256 + threadIdx.x;
    float* base = out + OFF_ENC + 2;
    const float4 z = make_float4(0.f, 0.f, 0.f, 0.f);
    long long s0 = gid * 4;
#pragma unroll
    for (int u = 0; u < 4; u++) {
        long long s = s0 + u;
        if (s < ENC_V4) *(float4*)(base + 4 * s) = z;
    }
    if (gid == 0) {
        out[OFF_ENC + 0] = 0.f;
        out[OFF_ENC + 1] = 0.f;
        out[OFF_ENC + ENC_F - 2] = 0.f;
        out[OFF_ENC + ENC_F - 1] = 0.f;
    }
}

// ---------------------------------------------------------------------------
// Kernel 3b: scatter the ones (runs after zero-fill, same stream).
// ---------------------------------------------------------------------------
__global__ __launch_bounds__(256) void k_enc_one(float* __restrict__ out) {
    const int t = blockIdx.x * 256 + threadIdx.x;
    out[OFF_ENC + (size_t)t * NK + g_idx[t]] = 1.f;
}

// ---------------------------------------------------------------------------
// Kernel 4: scalars — loss and perplexity
// ---------------------------------------------------------------------------
__global__ void k_final(float* __restrict__ out) {
    __shared__ double sh[NK];
    const int k = threadIdx.x;
    double p = (double)g_cnt[k] / (double)NTOK;
    sh[k] = p * log(p + 1e-10);
    __syncthreads();
    for (int s = 256; s; s >>= 1) {
        if (k < s) sh[k] += sh[k + s];
        __syncthreads();
    }
    if (k == 0) {
        out[OFF_PERP] = (float)exp(-sh[0]);
        out[OFF_LOSS] = (float)(1.25 * g_sum / (double)QELEMS);
    }
}

// ---------------------------------------------------------------------------
extern "C" void kernel_launch(void* const* d_in, const int* in_sizes, int n_in,
                              void* d_out, int out_size) {
    const float* p0 = (const float*)d_in[0];
    const float* p1 = (const float*)d_in[1];
    const float* x_in;
    const float* emb;
    if (in_sizes[0] == NK * ND) { emb = p0; x_in = p1; }
    else                        { x_in = p0; emb = p1; }
    float* out = (float*)d_out;

    k_init    <<<1, NK>>>(emb);
    k_argmin  <<<NTOK / 128, 256>>>(x_in, emb);
    k_quant   <<<NB * NH, 256>>>(x_in, emb, out);
    k_enc_zero<<<(int)((ENC_V4 + 1023) / 1024), 256>>>(out);
    k_enc_one <<<NTOK / 256, 256>>>(out);
    k_final   <<<1, NK>>>(out);
}

// round 8
// speedup vs baseline: 1.3327x; 1.3327x over previous
#include <cuda_runtime.h>
#include <cuda_bf16.h>
#include <math.h>
#include <stdint.h>
#include <float.h>

#define NB 16
#define NC 64
#define NH 128
#define NW 128
#define NK 512
#define ND 64
#define NHW (NH*NW)            // 16384
#define NTOK (NB*NHW)          // 262144
#define QELEMS (NB*NC*NHW)     // 1048576
#define OFF_LOSS 0
#define OFF_Q 1
#define OFF_PERP (1 + QELEMS)
#define OFF_ENC (2 + QELEMS)
#define ENC_F ((long long)NTOK * NK)
#define ENC_V4 ((ENC_F - 4) / 4)

#define CAND_MAX 24
#define TAU 4e-3f

__device__ unsigned     g_xb16[NTOK * 32];   // bf16-pair packed x  [tok][32]
__device__ unsigned     g_eb16[NK * 32];     // bf16-pair packed emb [code][32]
__device__ float        g_sx[NTOK];
__device__ float        g_e2[NK];
__device__ short        g_cand[NTOK * CAND_MAX];
__device__ int          g_ccnt[NTOK];
__device__ int          g_idx[NTOK];
__device__ unsigned     g_cnt[NK];
__device__ double       g_sum;

__device__ __forceinline__ uint32_t smem_u32(const void* p) {
    uint32_t a;
    asm("{ .reg .u64 t; cvta.to.shared.u64 t, %1; cvt.u32.u64 %0, t; }"
        : "=r"(a) : "l"(p));
    return a;
}
__device__ __forceinline__ void ldsm4(uint32_t* r, uint32_t addr) {
    asm volatile("ldmatrix.sync.aligned.m8n8.x4.shared.b16 {%0,%1,%2,%3}, [%4];"
                 : "=r"(r[0]), "=r"(r[1]), "=r"(r[2]), "=r"(r[3]) : "r"(addr));
}
__device__ __forceinline__ void mma_bf16(float* c, const uint32_t* a,
                                         const uint32_t b0, const uint32_t b1) {
    asm volatile(
        "mma.sync.aligned.m16n8k16.row.col.f32.bf16.bf16.f32 "
        "{%0,%1,%2,%3}, {%4,%5,%6,%7}, {%8,%9}, {%0,%1,%2,%3};"
        : "+f"(c[0]), "+f"(c[1]), "+f"(c[2]), "+f"(c[3])
        : "r"(a[0]), "r"(a[1]), "r"(a[2]), "r"(a[3]), "r"(b0), "r"(b1));
}

// ===================== Kernel: prep embedding =====================
__global__ void k_prep_emb(const float* __restrict__ emb) {
    int k = threadIdx.x;              // 512 threads
    if (k == 0) g_sum = 0.0;
    g_cnt[k] = 0u;
    const float* e = emb + k * ND;
    float s = 0.f;
    unsigned pk[32];
#pragma unroll
    for (int j = 0; j < 32; j++) {
        float v0 = e[2 * j], v1 = e[2 * j + 1];
        s = __fadd_rn(s, __fmul_rn(v0, v0));
        s = __fadd_rn(s, __fmul_rn(v1, v1));
        unsigned short h0 = __bfloat16_as_ushort(__float2bfloat16(v0));
        unsigned short h1 = __bfloat16_as_ushort(__float2bfloat16(v1));
        pk[j] = (unsigned)h0 | ((unsigned)h1 << 16);
    }
    g_e2[k] = s;
#pragma unroll
    for (int j = 0; j < 32; j++) g_eb16[k * 32 + j] = pk[j];
}

// ===================== Kernel: prep x (sx + bf16 convert) =====================
__global__ __launch_bounds__(256) void k_prep_x(const float* __restrict__ x_in) {
    __shared__ unsigned sb[256 * 33];
    const int tid = threadIdx.x;
    const int t   = blockIdx.x * 256 + tid;
    const int b   = t >> 14;
    const int hw  = t & (NHW - 1);
    const float* xp = x_in + (size_t)b * (NC * NHW) + hw;

    float sx = 0.f;
#pragma unroll
    for (int j = 0; j < 32; j++) {
        float v0 = xp[(size_t)(2 * j) * NHW];
        float v1 = xp[(size_t)(2 * j + 1) * NHW];
        sx = __fadd_rn(sx, __fmul_rn(v0, v0));
        sx = __fadd_rn(sx, __fmul_rn(v1, v1));
        unsigned short h0 = __bfloat16_as_ushort(__float2bfloat16(v0));
        unsigned short h1 = __bfloat16_as_ushort(__float2bfloat16(v1));
        sb[tid * 33 + j] = (unsigned)h0 | ((unsigned)h1 << 16);
    }
    g_sx[t] = sx;
    __syncthreads();
    const int base = blockIdx.x * 256 * 32;
    for (int i = tid; i < 256 * 32; i += 256) {
        int row = i >> 5, col = i & 31;
        g_xb16[base + i] = sb[row * 33 + col];
    }
}

// ===================== Kernel: mma.sync screening =====================
// CTA = 128 threads (4 warps), 128 tokens. 8 chunks of 64 codes.
// Warp w computes rows [32w,32w+32) x 64 codes via m16n8k16 bf16 MMA,
// dumps dot products to padded smem, all 128 threads then scan their
// token's 64 approx distances and keep candidates within TAU of min.
#define A_STRIDE 144              // bytes, conflict-free ldmatrix
#define B_STRIDE 144
#define D_STRIDE 72               // floats
#define SM_A     0
#define SM_B     (128 * A_STRIDE)                    // 18432
#define SM_D     (SM_B + 64 * B_STRIDE)              // 27648
#define SM_E2    (SM_D + 128 * D_STRIDE * 4)         // 64512
#define SMEM_SZ  (SM_E2 + NK * 4)                    // 66560

__global__ __launch_bounds__(128) void k_screen() {
    extern __shared__ char smem[];
    float* sD  = (float*)(smem + SM_D);
    float* se2 = (float*)(smem + SM_E2);

    const int tid  = threadIdx.x;
    const int wid  = tid >> 5;
    const int lane = tid & 31;
    const int tok0 = blockIdx.x * 128;

    // stage A: 128 token rows x 128B
    {
        const uint4* src = (const uint4*)(g_xb16 + (size_t)tok0 * 32);
        for (int i = tid; i < 128 * 8; i += 128) {
            int r = i >> 3, s = i & 7;
            *(uint4*)(smem + SM_A + r * A_STRIDE + s * 16) = src[i];
        }
    }
    for (int i = tid; i < NK; i += 128) se2[i] = g_e2[i];

    const float sx = g_sx[tok0 + tid];
    float m = FLT_MAX;
    int cnt = 0;
    const size_t cbase = (size_t)(tok0 + tid) * CAND_MAX;

    const uint32_t aB = smem_u32(smem + SM_A);
    const uint32_t bB = smem_u32(smem + SM_B);

    // A-fragment ldmatrix address (per lane), constant across chunks
    const int arow = wid * 32 + (lane & 7) + ((lane >> 3) & 1) * 8;
    const int abyt = (lane >> 4) * 16;
    // B-fragment address
    const int brow = ((lane >> 4) & 1) * 8 + (lane & 7);
    const int bbyt = ((lane >> 3) & 1) * 16;

#pragma unroll 1
    for (int ch = 0; ch < 8; ch++) {
        __syncthreads();
        {   // stage B chunk: 64 code rows x 128B
            const uint4* bs = (const uint4*)(g_eb16 + (size_t)ch * 64 * 32);
            for (int i = tid; i < 64 * 8; i += 128) {
                int r = i >> 3, s = i & 7;
                *(uint4*)(smem + SM_B + r * B_STRIDE + s * 16) = bs[i];
            }
        }
        __syncthreads();

        // load A fragments: [2 m-tiles][4 k-steps][4 regs]
        uint32_t a[2][4][4];
#pragma unroll
        for (int mt = 0; mt < 2; mt++)
#pragma unroll
            for (int ks = 0; ks < 4; ks++)
                ldsm4(a[mt][ks], aB + (arow + mt * 16) * A_STRIDE + ks * 32 + abyt);

        float c[2][8][4];
#pragma unroll
        for (int mt = 0; mt < 2; mt++)
#pragma unroll
            for (int nt = 0; nt < 8; nt++)
#pragma unroll
                for (int r = 0; r < 4; r++) c[mt][nt][r] = 0.f;

#pragma unroll
        for (int np = 0; np < 4; np++) {
            uint32_t bfr[4][4];   // [ks][{nt0lo, nt0hi, nt1lo, nt1hi}]
#pragma unroll
            for (int ks = 0; ks < 4; ks++)
                ldsm4(bfr[ks], bB + (np * 16 + brow) * B_STRIDE + ks * 32 + bbyt);
#pragma unroll
            for (int mt = 0; mt < 2; mt++)
#pragma unroll
                for (int ks = 0; ks < 4; ks++) {
                    mma_bf16(c[mt][2 * np + 0], a[mt][ks], bfr[ks][0], bfr[ks][1]);
                    mma_bf16(c[mt][2 * np + 1], a[mt][ks], bfr[ks][2], bfr[ks][3]);
                }
        }

        // dump dots to sD [128][72]
#pragma unroll
        for (int mt = 0; mt < 2; mt++) {
#pragma unroll
            for (int nt = 0; nt < 8; nt++) {
                int r0  = wid * 32 + mt * 16 + (lane >> 2);
                int col = nt * 8 + 2 * (lane & 3);
                *(float2*)&sD[r0 * D_STRIDE + col] =
                    make_float2(c[mt][nt][0], c[mt][nt][1]);
                *(float2*)&sD[(r0 + 8) * D_STRIDE + col] =
                    make_float2(c[mt][nt][2], c[mt][nt][3]);
            }
        }
        __syncthreads();

        // scan: thread tid owns token tok0+tid -> row tid
        const float* dr = sD + tid * D_STRIDE;
        const int code0 = ch * 64;
#pragma unroll
        for (int j = 0; j < 16; j++) {
            float4 f = *(const float4*)&dr[4 * j];
            const int cc = code0 + 4 * j;
            float d0 = __fsub_rn(__fadd_rn(sx, se2[cc + 0]), 2.0f * f.x);
            float d1 = __fsub_rn(__fadd_rn(sx, se2[cc + 1]), 2.0f * f.y);
            float d2 = __fsub_rn(__fadd_rn(sx, se2[cc + 2]), 2.0f * f.z);
            float d3 = __fsub_rn(__fadd_rn(sx, se2[cc + 3]), 2.0f * f.w);
            if (d0 <= m + TAU) { if (cnt < CAND_MAX) g_cand[cbase + cnt] = (short)(cc + 0); cnt++; }
            if (d0 < m) m = d0;
            if (d1 <= m + TAU) { if (cnt < CAND_MAX) g_cand[cbase + cnt] = (short)(cc + 1); cnt++; }
            if (d1 < m) m = d1;
            if (d2 <= m + TAU) { if (cnt < CAND_MAX) g_cand[cbase + cnt] = (short)(cc + 2); cnt++; }
            if (d2 < m) m = d2;
            if (d3 <= m + TAU) { if (cnt < CAND_MAX) g_cand[cbase + cnt] = (short)(cc + 3); cnt++; }
            if (d3 < m) m = d3;
        }
    }

    g_ccnt[tok0 + tid] = cnt;
}

// ===================== Kernel: exact refine =====================
// Recompute EXACT reference-rounded fp32 distances for candidates only
// (sequential fmaf over ascending d — bitwise identical to the R1/R2
// kernels that passed). Smallest-index tie-break.
__global__ __launch_bounds__(256) void k_refine(const float* __restrict__ x_in,
                                                const float* __restrict__ emb) {
    __shared__ unsigned scnt[NK];
    const int tid = threadIdx.x;
    const int t   = blockIdx.x * 256 + tid;
    const int b   = t >> 14;
    const int hw  = t & (NHW - 1);

    for (int i = tid; i < NK; i += 256) scnt[i] = 0u;

    const float* xp = x_in + (size_t)b * (NC * NHW) + hw;
    float x[ND];
#pragma unroll
    for (int d = 0; d < ND; d++) x[d] = xp[(size_t)d * NHW];

    const float sx = g_sx[t];
    const int cnt = g_ccnt[t];
    float best = FLT_MAX;
    int   bk   = 0;

    if (cnt <= CAND_MAX) {
        for (int i = 0; i < cnt; i++) {
            int k = g_cand[(size_t)t * CAND_MAX + i];
            const float4* er = (const float4*)(emb + (size_t)k * ND);
            float dot = 0.f;
#pragma unroll
            for (int j = 0; j < 16; j++) {
                float4 e = er[j];
                dot = fmaf(x[4 * j + 0], e.x, dot);
                dot = fmaf(x[4 * j + 1], e.y, dot);
                dot = fmaf(x[4 * j + 2], e.z, dot);
                dot = fmaf(x[4 * j + 3], e.w, dot);
            }
            float dd = __fsub_rn(__fadd_rn(sx, g_e2[k]), 2.0f * dot);
            if (dd < best || (dd == best && k < bk)) { best = dd; bk = k; }
        }
    } else {   // overflow fallback: full exact scan (ascending k, strict <)
        for (int k = 0; k < NK; k++) {
            const float4* er = (const float4*)(emb + (size_t)k * ND);
            float dot = 0.f;
#pragma unroll
            for (int j = 0; j < 16; j++) {
                float4 e = er[j];
                dot = fmaf(x[4 * j + 0], e.x, dot);
                dot = fmaf(x[4 * j + 1], e.y, dot);
                dot = fmaf(x[4 * j + 2], e.z, dot);
                dot = fmaf(x[4 * j + 3], e.w, dot);
            }
            float dd = __fsub_rn(__fadd_rn(sx, g_e2[k]), 2.0f * dot);
            if (dd < best) { best = dd; bk = k; }
        }
    }

    g_idx[t] = bk;
    __syncthreads();
    atomicAdd(&scnt[bk], 1u);
    __syncthreads();
    for (int i = tid; i < NK; i += 256)
        if (scnt[i]) atomicAdd(&g_cnt[i], scnt[i]);
}

// ===================== Kernel: quantize + loss =====================
__global__ __launch_bounds__(256) void k_quant(const float* __restrict__ x_in,
                                               const float* __restrict__ emb,
                                               float* __restrict__ out) {
    __shared__ float sq[128 * 65];
    __shared__ int   sidx[128];
    __shared__ float spart[8];

    const int tid = threadIdx.x;
    const int bh  = blockIdx.x;
    const int b   = bh >> 7;
    const int h   = bh & 127;

    if (tid < 128) sidx[tid] = g_idx[b * NHW + h * NW + tid];
    __syncthreads();

    for (int i = tid; i < 128 * ND; i += 256) {
        int w = i >> 6, d = i & 63;
        sq[w * 65 + d] = emb[(size_t)sidx[w] * ND + d];
    }
    __syncthreads();

    const float* xb = x_in + (size_t)b * NC * NHW + h * NW;
    float*       qb = out + OFF_Q + (size_t)b * NC * NHW + h * NW;

    float ls = 0.f;
    for (int i = tid; i < NC * NW; i += 256) {
        int c = i >> 7, w = i & 127;
        float q  = sq[w * 65 + c];
        float xv = xb[(size_t)c * NHW + w];
        float dd = q - xv;
        ls += dd * dd;
        qb[(size_t)c * NHW + w] = q;
    }

    for (int o = 16; o; o >>= 1) ls += __shfl_xor_sync(0xffffffffu, ls, o);
    if ((tid & 31) == 0) spart[tid >> 5] = ls;
    __syncthreads();
    if (tid == 0) {
        float s = 0.f;
        for (int i = 0; i < 8; i++) s += spart[i];
        atomicAdd(&g_sum, (double)s);
    }
}

// ===================== Kernels: encodings =====================
__global__ __launch_bounds__(256) void k_enc_zero(float* __restrict__ out) {
    const long long gid = (long long)blockIdx.x * 256 + threadIdx.x;
    float* base = out + OFF_ENC + 2;
    const float4 z = make_float4(0.f, 0.f, 0.f, 0.f);
    long long s0 = gid * 4;
#pragma unroll
    for (int u = 0; u < 4; u++) {
        long long s = s0 + u;
        if (s < ENC_V4) *(float4*)(base + 4 * s) = z;
    }
    if (gid == 0) {
        out[OFF_ENC + 0] = 0.f;
        out[OFF_ENC + 1] = 0.f;
        out[OFF_ENC + ENC_F - 2] = 0.f;
        out[OFF_ENC + ENC_F - 1] = 0.f;
    }
}
__global__ __launch_bounds__(256) void k_enc_one(float* __restrict__ out) {
    const int t = blockIdx.x * 256 + threadIdx.x;
    out[OFF_ENC + (size_t)t * NK + g_idx[t]] = 1.f;
}

// ===================== Kernel: scalars =====================
__global__ void k_final(float* __restrict__ out) {
    __shared__ double sh[NK];
    const int k = threadIdx.x;
    double p = (double)g_cnt[k] / (double)NTOK;
    sh[k] = p * log(p + 1e-10);
    __syncthreads();
    for (int s = 256; s; s >>= 1) {
        if (k < s) sh[k] += sh[k + s];
        __syncthreads();
    }
    if (k == 0) {
        out[OFF_PERP] = (float)exp(-sh[0]);
        out[OFF_LOSS] = (float)(1.25 * g_sum / (double)QELEMS);
    }
}

// ===================== host =====================
extern "C" void kernel_launch(void* const* d_in, const int* in_sizes, int n_in,
                              void* d_out, int out_size) {
    const float* p0 = (const float*)d_in[0];
    const float* p1 = (const float*)d_in[1];
    const float* x_in;
    const float* emb;
    if (in_sizes[0] == NK * ND) { emb = p0; x_in = p1; }
    else                        { x_in = p0; emb = p1; }
    float* out = (float*)d_out;

    // Unconditional + idempotent (no static guards — harness rule).
    cudaFuncSetAttribute(k_screen, cudaFuncAttributeMaxDynamicSharedMemorySize,
                         SMEM_SZ);

    k_prep_emb<<<1, NK>>>(emb);
    k_prep_x  <<<NTOK / 256, 256>>>(x_in);
    k_screen  <<<NTOK / 128, 128, SMEM_SZ>>>();
    k_refine  <<<NTOK / 256, 256>>>(x_in, emb);
    k_quant   <<<NB * NH, 256>>>(x_in, emb, out);
    k_enc_zero<<<(int)((ENC_V4 + 1023) / 1024), 256>>>(out);
    k_enc_one <<<NTOK / 256, 256>>>(out);
    k_final   <<<1, NK>>>(out);
}